// round 5
// baseline (speedup 1.0000x reference)
#include <cuda_runtime.h>
#include <cuda_bf16.h>
#include <cstdint>
#include <cstddef>

// ---------------------------------------------------------------------------
// Problem constants
// ---------------------------------------------------------------------------
#define BATCH   8
#define SEQ     2048
#define DIM     1024
#define HEADS   16
#define HDIM    64
#define TOKENS  (BATCH * SEQ)          // 16384
#define ELEMS   (TOKENS * DIM)         // 16,777,216

// ---------------------------------------------------------------------------
// Scratch (allocation-free rule: __device__ globals)
// ---------------------------------------------------------------------------
__device__ __align__(256) float g_Q[ELEMS];
__device__ __align__(256) float g_K[ELEMS];
__device__ __align__(256) float g_V[ELEMS];
__device__ __align__(256) float g_Y[ELEMS];
__device__ __align__(256) __nv_bfloat16 g_Whi[4][DIM * DIM];
__device__ __align__(256) __nv_bfloat16 g_Wlo[4][DIM * DIM];

// ---------------------------------------------------------------------------
// PTX helpers (sm_80-level only; tcgen05 rejected by compute_103 virtual arch)
// ---------------------------------------------------------------------------
__device__ __forceinline__ uint32_t smem_u32(const void* p) {
    uint32_t a;
    asm("{ .reg .u64 t; cvta.to.shared.u64 t, %1; cvt.u32.u64 %0, t; }"
        : "=r"(a) : "l"(p));
    return a;
}

__device__ __forceinline__ void cp_async16(uint32_t dst, const void* src) {
    asm volatile("cp.async.cg.shared.global [%0], [%1], 16;"
                 :: "r"(dst), "l"(src) : "memory");
}
__device__ __forceinline__ void cp_commit() {
    asm volatile("cp.async.commit_group;" ::: "memory");
}
template <int N>
__device__ __forceinline__ void cp_wait() {
    asm volatile("cp.async.wait_group %0;" :: "n"(N) : "memory");
}

__device__ __forceinline__ void ldm_x4(uint32_t* r, uint32_t addr) {
    asm volatile("ldmatrix.sync.aligned.m8n8.x4.shared.b16 {%0,%1,%2,%3}, [%4];"
                 : "=r"(r[0]), "=r"(r[1]), "=r"(r[2]), "=r"(r[3])
                 : "r"(addr));
}

__device__ __forceinline__ void mma_bf16(float* c, const uint32_t* a,
                                         const uint32_t* b) {
    asm volatile(
        "mma.sync.aligned.m16n8k16.row.col.f32.bf16.bf16.f32 "
        "{%0,%1,%2,%3}, {%4,%5,%6,%7}, {%8,%9}, {%0,%1,%2,%3};"
        : "+f"(c[0]), "+f"(c[1]), "+f"(c[2]), "+f"(c[3])
        : "r"(a[0]), "r"(a[1]), "r"(a[2]), "r"(a[3]), "r"(b[0]), "r"(b[1]));
}

__device__ __forceinline__ uint32_t pack_bf16(float x, float y) {
    return (uint32_t)__bfloat16_as_ushort(__float2bfloat16(x))
         | ((uint32_t)__bfloat16_as_ushort(__float2bfloat16(y)) << 16);
}

// ---------------------------------------------------------------------------
// fp32 -> bf16 hi/lo split (weights only; 4 elems / thread)
// ---------------------------------------------------------------------------
__global__ __launch_bounds__(256) void convert_kernel(
    const float* __restrict__ x, __nv_bfloat16* __restrict__ hi,
    __nv_bfloat16* __restrict__ lo, int n4)
{
    int i = blockIdx.x * blockDim.x + threadIdx.x;
    if (i >= n4) return;
    float4 v = reinterpret_cast<const float4*>(x)[i];
    float h0 = __bfloat162float(__float2bfloat16(v.x));
    float h1 = __bfloat162float(__float2bfloat16(v.y));
    float h2 = __bfloat162float(__float2bfloat16(v.z));
    float h3 = __bfloat162float(__float2bfloat16(v.w));
    uint2 hp = make_uint2(pack_bf16(v.x, v.y), pack_bf16(v.z, v.w));
    uint2 lp = make_uint2(pack_bf16(v.x - h0, v.y - h1),
                          pack_bf16(v.z - h2, v.w - h3));
    reinterpret_cast<uint2*>(hi)[i] = hp;
    reinterpret_cast<uint2*>(lo)[i] = lp;
}

// ---------------------------------------------------------------------------
// bf16x3-split GEMM-NT on mma.sync with FUSED fp32->hi/lo split of A:
//   C = A @ (Bhi+Blo)^T (+bias),  A fp32 [M,K], B bf16 hi/lo [N,K].
//   CTA 128x128, K-chunk 64, 2-stage cp.async pipeline.
//   Per chunk: stage A fp32 (32KB) -> in-smem split to Ahi/Alo bf16 tiles.
//   8 warps (2x4), warp tile 64x32, sequential term phases (hh, lh, hl).
// Stage (64KB): Afp32@0 (32K) | Bhi@32K (16K) | Blo@48K (16K)
// Ahi/Alo single buffers after the 2 stages (16K each).
// bf16 tile rows: 128B, 16B-block swizzle (row,c16)->row*128+16*(c16^(row&7)).
// ---------------------------------------------------------------------------
#define GBM 128
#define GBN 128
#define GKC 64
#define STAGE_BYTES 65536
#define AHI_OFF (2 * STAGE_BYTES)            // 131072
#define ALO_OFF (AHI_OFF + 16384)            // 147456
#define GEMM_SMEM (ALO_OFF + 16384)          // 163840 (160 KB)

__global__ __launch_bounds__(256, 1) void gemm_mma_kernel(
    const float* __restrict__ A,
    const __nv_bfloat16* __restrict__ Bhi, const __nv_bfloat16* __restrict__ Blo,
    const float* __restrict__ bias, float* __restrict__ C)
{
    extern __shared__ char smem[];
    const uint32_t sbase = smem_u32(smem);

    const int tid  = threadIdx.x;
    const int wid  = tid >> 5;
    const int lane = tid & 31;
    const int wm   = wid & 1;            // 2 warp-rows (64 rows each)
    const int wn   = wid >> 1;           // 4 warp-cols (32 cols each)
    const int row0 = blockIdx.y * GBM;
    const int col0 = blockIdx.x * GBN;

    const int laneRow = (lane & 7) + ((lane >> 3) & 1) * 8;
    const int hb      = (lane >> 4) & 1;          // 16B half selector

    uint32_t aRow[4], aXor[4], bRow[2], bXor[2];
    #pragma unroll
    for (int mi = 0; mi < 4; mi++) {
        const int r = wm * 64 + mi * 16 + laneRow;
        aRow[mi] = (uint32_t)(r * 128);
        aXor[mi] = (uint32_t)(r & 7);
    }
    #pragma unroll
    for (int p = 0; p < 2; p++) {
        const int r = wn * 32 + p * 16 + laneRow;
        bRow[p] = (uint32_t)(r * 128);
        bXor[p] = (uint32_t)(r & 7);
    }

    float acc[4][4][4];
    #pragma unroll
    for (int mi = 0; mi < 4; mi++)
        #pragma unroll
        for (int ni = 0; ni < 4; ni++)
            #pragma unroll
            for (int r = 0; r < 4; r++) acc[mi][ni][r] = 0.f;

    // chunk loader: A fp32 2048 x 16B + B hi/lo 2048 x 16B = 16 / thread
    auto load_chunk = [&](int stage, int k0) {
        const uint32_t sb = sbase + stage * STAGE_BYTES;
        #pragma unroll
        for (int it = 0; it < 8; it++) {
            const int i = tid + it * 256;
            const int r = i >> 4, c4 = i & 15;
            cp_async16(sb + r * 256 + c4 * 16,
                       A + (size_t)(row0 + r) * DIM + k0 + c4 * 4);
        }
        #pragma unroll
        for (int it = 0; it < 8; it++) {
            const int i = tid + it * 256;
            const int j = i & 1023, r = j >> 3, c = j & 7;
            const __nv_bfloat16* base = (i < 1024) ? Bhi : Blo;
            const uint32_t off = (i < 1024) ? 32768u : 49152u;
            cp_async16(sb + off + r * 128 + 16 * (c ^ (r & 7)),
                       base + (size_t)(col0 + r) * DIM + k0 + c * 8);
        }
    };

    load_chunk(0, 0);
    cp_commit();

    const int NCHUNK = DIM / GKC;   // 16
    for (int c = 0; c < NCHUNK; c++) {
        const int s = c & 1;
        if (c + 1 < NCHUNK) {
            load_chunk(s ^ 1, (c + 1) * GKC);   // stage s^1: safe, end-sync of c-1
            cp_commit();
            cp_wait<1>();
        } else {
            cp_wait<0>();
        }
        __syncthreads();

        // in-smem split: A fp32 staging -> Ahi/Alo bf16 swizzled tiles
        {
            const uint32_t st = sbase + s * STAGE_BYTES;
            #pragma unroll
            for (int it = 0; it < 8; it++) {
                const int i = tid + it * 256;
                const int r = i >> 4, c4 = i & 15;
                float4 v = *reinterpret_cast<const float4*>(
                    smem + (st - sbase) + r * 256 + c4 * 16);
                float h0 = __bfloat162float(__float2bfloat16(v.x));
                float h1 = __bfloat162float(__float2bfloat16(v.y));
                float h2 = __bfloat162float(__float2bfloat16(v.z));
                float h3 = __bfloat162float(__float2bfloat16(v.w));
                uint2 hp = make_uint2(pack_bf16(v.x, v.y), pack_bf16(v.z, v.w));
                uint2 lp = make_uint2(pack_bf16(v.x - h0, v.y - h1),
                                      pack_bf16(v.z - h2, v.w - h3));
                const uint32_t boff = r * 128 + 16 * ((c4 >> 1) ^ (r & 7))
                                    + (c4 & 1) * 8;
                *reinterpret_cast<uint2*>(smem + AHI_OFF + boff) = hp;
                *reinterpret_cast<uint2*>(smem + ALO_OFF + boff) = lp;
            }
        }
        __syncthreads();

        const uint32_t sAh = sbase + AHI_OFF;
        const uint32_t sAl = sbase + ALO_OFF;
        const uint32_t sBh = sbase + s * STAGE_BYTES + 32768u;
        const uint32_t sBl = sbase + s * STAGE_BYTES + 49152u;

        #pragma unroll
        for (int ks = 0; ks < 4; ks++) {
            const uint32_t ck = (uint32_t)(2 * ks + hb);   // 16B column index
            uint32_t a[4][4], b[4][2];

            // phase 1: hh
            #pragma unroll
            for (int mi = 0; mi < 4; mi++)
                ldm_x4(a[mi], sAh + aRow[mi] + 16 * (ck ^ aXor[mi]));
            #pragma unroll
            for (int p = 0; p < 2; p++) {
                uint32_t r[4];
                ldm_x4(r, sBh + bRow[p] + 16 * (ck ^ bXor[p]));
                b[2*p][0] = r[0]; b[2*p][1] = r[2];
                b[2*p+1][0] = r[1]; b[2*p+1][1] = r[3];
            }
            #pragma unroll
            for (int mi = 0; mi < 4; mi++)
                #pragma unroll
                for (int ni = 0; ni < 4; ni++)
                    mma_bf16(acc[mi][ni], a[mi], b[ni]);

            // phase 2: lh (a <- Alo)
            #pragma unroll
            for (int mi = 0; mi < 4; mi++)
                ldm_x4(a[mi], sAl + aRow[mi] + 16 * (ck ^ aXor[mi]));
            #pragma unroll
            for (int mi = 0; mi < 4; mi++)
                #pragma unroll
                for (int ni = 0; ni < 4; ni++)
                    mma_bf16(acc[mi][ni], a[mi], b[ni]);

            // phase 3: hl (a <- Ahi, b <- Blo)
            #pragma unroll
            for (int mi = 0; mi < 4; mi++)
                ldm_x4(a[mi], sAh + aRow[mi] + 16 * (ck ^ aXor[mi]));
            #pragma unroll
            for (int p = 0; p < 2; p++) {
                uint32_t r[4];
                ldm_x4(r, sBl + bRow[p] + 16 * (ck ^ bXor[p]));
                b[2*p][0] = r[0]; b[2*p][1] = r[2];
                b[2*p+1][0] = r[1]; b[2*p+1][1] = r[3];
            }
            #pragma unroll
            for (int mi = 0; mi < 4; mi++)
                #pragma unroll
                for (int ni = 0; ni < 4; ni++)
                    mma_bf16(acc[mi][ni], a[mi], b[ni]);
        }
        __syncthreads();
    }

    // epilogue
    const int g  = lane >> 2;
    const int tg = lane & 3;
    #pragma unroll
    for (int mi = 0; mi < 4; mi++) {
        const int r0 = row0 + wm * 64 + mi * 16 + g;
        #pragma unroll
        for (int ni = 0; ni < 4; ni++) {
            const int cc = col0 + wn * 32 + ni * 8 + tg * 2;
            float b0 = 0.f, b1 = 0.f;
            if (bias) { b0 = bias[cc]; b1 = bias[cc + 1]; }
            float2 v0 = make_float2(acc[mi][ni][0] + b0, acc[mi][ni][1] + b1);
            float2 v1 = make_float2(acc[mi][ni][2] + b0, acc[mi][ni][3] + b1);
            *reinterpret_cast<float2*>(&C[(size_t)r0 * DIM + cc]) = v0;
            *reinterpret_cast<float2*>(&C[(size_t)(r0 + 8) * DIM + cc]) = v1;
        }
    }
}

// ---------------------------------------------------------------------------
// Per-token head-mixing attention + permuted fp32 store.
// ---------------------------------------------------------------------------
__global__ __launch_bounds__(128) void attn_kernel(
    const float* __restrict__ Q, const float* __restrict__ K,
    const float* __restrict__ V, float* __restrict__ Y)
{
    const int t = blockIdx.x;
    const int n = t & (SEQ - 1);
    const int b = t >> 11;

    const float* q = Q + (size_t)t * DIM;
    const float* k = K + (size_t)t * DIM;
    const float* v = V + (size_t)t * DIM;

    __shared__ float sq[HEADS * 65];
    __shared__ float sk[HEADS * 65];
    __shared__ float sv[DIM];
    __shared__ float sl[HEADS * HEADS];

    const int tid = threadIdx.x;

    #pragma unroll
    for (int i = tid; i < 256; i += 128) {
        const int r = i >> 4;
        const int c = (i & 15) << 2;
        float4 a = reinterpret_cast<const float4*>(q)[i];
        sq[r * 65 + c + 0] = a.x; sq[r * 65 + c + 1] = a.y;
        sq[r * 65 + c + 2] = a.z; sq[r * 65 + c + 3] = a.w;
        float4 bb = reinterpret_cast<const float4*>(k)[i];
        sk[r * 65 + c + 0] = bb.x; sk[r * 65 + c + 1] = bb.y;
        sk[r * 65 + c + 2] = bb.z; sk[r * 65 + c + 3] = bb.w;
        reinterpret_cast<float4*>(sv)[i] = reinterpret_cast<const float4*>(v)[i];
    }
    __syncthreads();

    #pragma unroll
    for (int e = tid; e < 256; e += 128) {
        const int h = e >> 4;
        const int gg = e & 15;
        float s = 0.f;
        #pragma unroll
        for (int d = 0; d < HDIM; d++)
            s += sq[h * 65 + d] * sk[gg * 65 + d];
        sl[h * 16 + gg] = s * 0.125f;
    }
    __syncthreads();

    if (tid < HEADS) {
        float mx = -1e30f;
        #pragma unroll
        for (int gg = 0; gg < 16; gg++) mx = fmaxf(mx, sl[tid * 16 + gg]);
        float sum = 0.f;
        #pragma unroll
        for (int gg = 0; gg < 16; gg++) {
            const float e = __expf(sl[tid * 16 + gg] - mx);
            sl[tid * 16 + gg] = e;
            sum += e;
        }
        const float inv = 1.f / sum;
        #pragma unroll
        for (int gg = 0; gg < 16; gg++) sl[tid * 16 + gg] *= inv;
    }
    __syncthreads();

    float* yb = Y + (size_t)b * (SEQ * DIM);
    #pragma unroll
    for (int e = tid; e < 1024; e += 128) {
        const int h = e >> 6;
        const int d = e & 63;
        float s = 0.f;
        #pragma unroll
        for (int gg = 0; gg < 16; gg++)
            s += sl[h * 16 + gg] * sv[gg * 64 + d];
        const int nn = h * 128 + (n >> 4);
        const int cc = ((n & 15) << 6) + d;
        yb[(size_t)nn * DIM + cc] = s;
    }
}

// ---------------------------------------------------------------------------
// kernel_launch
// ---------------------------------------------------------------------------
extern "C" void kernel_launch(void* const* d_in, const int* in_sizes, int n_in,
                              void* d_out, int out_size)
{
    const float* query = (const float*)d_in[0];
    const float* key   = (const float*)d_in[1];
    const float* value = (const float*)d_in[2];
    const float* W[4]  = { (const float*)d_in[5], (const float*)d_in[6],
                           (const float*)d_in[7], (const float*)d_in[8] };
    const float* bp    = (const float*)d_in[9];
    float* out = (float*)d_out;

    float *Qb, *Kb, *Vb, *Yb;
    __nv_bfloat16 *Whi, *Wlo;
    cudaGetSymbolAddress((void**)&Qb, g_Q);
    cudaGetSymbolAddress((void**)&Kb, g_K);
    cudaGetSymbolAddress((void**)&Vb, g_V);
    cudaGetSymbolAddress((void**)&Yb, g_Y);
    cudaGetSymbolAddress((void**)&Whi, g_Whi);
    cudaGetSymbolAddress((void**)&Wlo, g_Wlo);

    cudaFuncSetAttribute(gemm_mma_kernel,
                         cudaFuncAttributeMaxDynamicSharedMemorySize, GEMM_SMEM);

    // weight hi/lo splits (small, L2-resident afterwards)
    for (int w = 0; w < 4; w++)
        convert_kernel<<<1024, 256>>>(W[w], Whi + (size_t)w * DIM * DIM,
                                      Wlo + (size_t)w * DIM * DIM, DIM * DIM / 4);

    const dim3 ggrid(DIM / GBN, TOKENS / GBM);   // (8, 128) = 1024 CTAs
    gemm_mma_kernel<<<ggrid, 256, GEMM_SMEM>>>(query, Whi + 0 * (size_t)DIM * DIM,
                                               Wlo + 0 * (size_t)DIM * DIM, nullptr, Qb);
    gemm_mma_kernel<<<ggrid, 256, GEMM_SMEM>>>(key,   Whi + 1 * (size_t)DIM * DIM,
                                               Wlo + 1 * (size_t)DIM * DIM, nullptr, Kb);
    gemm_mma_kernel<<<ggrid, 256, GEMM_SMEM>>>(value, Whi + 2 * (size_t)DIM * DIM,
                                               Wlo + 2 * (size_t)DIM * DIM, nullptr, Vb);

    attn_kernel<<<TOKENS, 128>>>(Qb, Kb, Vb, Yb);

    gemm_mma_kernel<<<ggrid, 256, GEMM_SMEM>>>(Yb, Whi + 3 * (size_t)DIM * DIM,
                                               Wlo + 3 * (size_t)DIM * DIM, bp, out);
}

// round 6
// speedup vs baseline: 1.2835x; 1.2835x over previous
#include <cuda_runtime.h>
#include <cuda_bf16.h>
#include <cstdint>
#include <cstddef>

// ---------------------------------------------------------------------------
// Problem constants
// ---------------------------------------------------------------------------
#define BATCH   8
#define SEQ     2048
#define DIM     1024
#define HEADS   16
#define HDIM    64
#define TOKENS  (BATCH * SEQ)          // 16384
#define ELEMS   (TOKENS * DIM)         // 16,777,216

// ---------------------------------------------------------------------------
// Scratch (allocation-free rule: __device__ globals)
// ---------------------------------------------------------------------------
__device__ __align__(256) float g_Q[ELEMS];
__device__ __align__(256) float g_K[ELEMS];
__device__ __align__(256) float g_V[ELEMS];
__device__ __align__(256) float g_Y[ELEMS];
__device__ __align__(256) float g_Wt[4][DIM * DIM];   // tf32-rounded, interleaved

// ---------------------------------------------------------------------------
// PTX helpers (sm_80-level; tcgen05 rejected by compute_103 virtual arch)
// ---------------------------------------------------------------------------
__device__ __forceinline__ uint32_t smem_u32(const void* p) {
    uint32_t a;
    asm("{ .reg .u64 t; cvta.to.shared.u64 t, %1; cvt.u32.u64 %0, t; }"
        : "=r"(a) : "l"(p));
    return a;
}

__device__ __forceinline__ void cp_async16(uint32_t dst, const void* src) {
    asm volatile("cp.async.cg.shared.global [%0], [%1], 16;"
                 :: "r"(dst), "l"(src) : "memory");
}
__device__ __forceinline__ void cp_commit() {
    asm volatile("cp.async.commit_group;" ::: "memory");
}
template <int N>
__device__ __forceinline__ void cp_wait() {
    asm volatile("cp.async.wait_group %0;" :: "n"(N) : "memory");
}

__device__ __forceinline__ uint32_t f2tf32(float x) {
    uint32_t r;
    asm("cvt.rna.tf32.f32 %0, %1;" : "=r"(r) : "f"(x));
    return r;
}

// m16n8k8 tf32 MMA, fp32 accum
__device__ __forceinline__ void mma_tf32(float* c, const uint32_t* a,
                                         uint32_t b0, uint32_t b1) {
    asm volatile(
        "mma.sync.aligned.m16n8k8.row.col.f32.tf32.tf32.f32 "
        "{%0,%1,%2,%3}, {%4,%5,%6,%7}, {%8,%9}, {%0,%1,%2,%3};"
        : "+f"(c[0]), "+f"(c[1]), "+f"(c[2]), "+f"(c[3])
        : "r"(a[0]), "r"(a[1]), "r"(a[2]), "r"(a[3]), "r"(b0), "r"(b1));
}

// ---------------------------------------------------------------------------
// Weight prep: tf32-round + interleave.
//   in:  W[n][k] fp32 row-major (torch Linear [out,in])
//   out: Wt[n][ (k/32)*32 + (k%4)*8 + (k%32)/4 ]  (tf32-rounded fp32)
// This makes each 16B gmem piece land contiguously in the GEMM's smem
// c-block layout (c = k mod 4 owns words (k/4) within the K-chunk).
// ---------------------------------------------------------------------------
__global__ __launch_bounds__(256) void prep_w_kernel(
    const float* __restrict__ W0, const float* __restrict__ W1,
    const float* __restrict__ W2, const float* __restrict__ W3,
    float* __restrict__ Wt)
{
    const int i = blockIdx.x * blockDim.x + threadIdx.x;   // over 4M elems
    const int w = i >> 20;
    const int e = i & ((1 << 20) - 1);
    const float* src = (w == 0) ? W0 : (w == 1) ? W1 : (w == 2) ? W2 : W3;
    const int n = e >> 10, k = e & 1023;
    const int kc = k >> 5, km = k & 31, c = km & 3, k4 = km >> 2;
    const uint32_t v = f2tf32(src[(size_t)n * DIM + k]);
    reinterpret_cast<uint32_t*>(Wt)[(size_t)w * DIM * DIM
        + (size_t)n * DIM + kc * 32 + c * 8 + k4] = v;
}

// ---------------------------------------------------------------------------
// TF32 GEMM-NT:  C = A @ B^T (+bias);  A fp32 [M,K], Bt prepped weights.
//   CTA 128x256, 8 warps (2x4), warp tile 64x64, K-chunk 32, 3-stage pipeline.
// smem per stage (67584 B):
//   A @0:      128 rows x 144B (32 fp32 + 16B pad; stride 36 words = 4 mod 32
//              -> scalar LDS banks 4g+c, conflict-free)
//   B @18432:  256 rows x 192B (4 c-blocks of 12 words: 8 data + 4 pad
//              -> LDS.128 fragment loads conflict-free)
// grid.z selects (A,B,C) triple -> merged Q/K/V launch.
// ---------------------------------------------------------------------------
#define GBM 128
#define GBN 256
#define GKC 32
#define A_STAGE 18432
#define B_STAGE 49152
#define STAGE_BYTES (A_STAGE + B_STAGE)      // 67584
#define NSTAGE 3
#define GEMM_SMEM (NSTAGE * STAGE_BYTES)     // 202752

__global__ __launch_bounds__(256, 1) void gemm_tf32_kernel(
    const float* __restrict__ A0, const float* __restrict__ A1,
    const float* __restrict__ A2,
    const float* __restrict__ B0, const float* __restrict__ B1,
    const float* __restrict__ B2,
    float* __restrict__ C0, float* __restrict__ C1, float* __restrict__ C2,
    const float* __restrict__ bias)
{
    const float* A = (blockIdx.z == 0) ? A0 : (blockIdx.z == 1) ? A1 : A2;
    const float* B = (blockIdx.z == 0) ? B0 : (blockIdx.z == 1) ? B1 : B2;
    float*       C = (blockIdx.z == 0) ? C0 : (blockIdx.z == 1) ? C1 : C2;

    extern __shared__ char smem[];
    const uint32_t sbase = smem_u32(smem);

    const int tid  = threadIdx.x;
    const int wid  = tid >> 5;
    const int lane = tid & 31;
    const int wm   = wid & 1;            // 2 warp-rows (64 rows each)
    const int wn   = wid >> 1;           // 4 warp-cols (64 cols each)
    const int row0 = blockIdx.y * GBM;
    const int col0 = blockIdx.x * GBN;

    const int g = lane >> 2;             // groupID (0..7)
    const int c = lane & 3;              // threadID_in_group

    // per-lane smem word bases
    uint32_t aBase[4];                   // A row base per mi (words)
    #pragma unroll
    for (int mi = 0; mi < 4; mi++)
        aBase[mi] = (uint32_t)((wm * 64 + mi * 16 + g) * 36 + c);
    uint32_t bBase[8];                   // B row base per ni (bytes)
    #pragma unroll
    for (int ni = 0; ni < 8; ni++)
        bBase[ni] = (uint32_t)((wn * 64 + ni * 8 + g) * 192 + c * 48);

    float acc[4][8][4];
    #pragma unroll
    for (int mi = 0; mi < 4; mi++)
        #pragma unroll
        for (int ni = 0; ni < 8; ni++)
            #pragma unroll
            for (int r = 0; r < 4; r++) acc[mi][ni][r] = 0.f;

    // chunk loader: A 1024 + B 2048 16B pieces = 12 per thread
    auto load_chunk = [&](int stage, int kc) {
        const uint32_t sb = sbase + stage * STAGE_BYTES;
        #pragma unroll
        for (int it = 0; it < 4; it++) {
            const int i = tid + it * 256;
            const int r = i >> 3, c4 = i & 7;
            cp_async16(sb + r * 144 + c4 * 16,
                       A + (size_t)(row0 + r) * DIM + kc * 32 + c4 * 4);
        }
        #pragma unroll
        for (int it = 0; it < 8; it++) {
            const int i = tid + it * 256;
            const int r = i >> 3, p = i & 7;
            cp_async16(sb + A_STAGE + r * 192 + (p >> 1) * 48 + (p & 1) * 16,
                       B + (size_t)(col0 + r) * DIM + kc * 32 + p * 4);
        }
    };

    load_chunk(0, 0);
    cp_commit();
    load_chunk(1, 1);
    cp_commit();

    const int NCHUNK = DIM / GKC;   // 32
    for (int ch = 0; ch < NCHUNK; ch++) {
        if (ch + 2 < NCHUNK) cp_wait<1>(); else cp_wait<0>();
        __syncthreads();
        if (ch + 2 < NCHUNK) {
            load_chunk((ch + 2) % NSTAGE, ch + 2);
            cp_commit();
        }

        const uint32_t sb = sbase + (ch % NSTAGE) * STAGE_BYTES;
        const uint32_t sA = sb;               // word-addressed below
        const uint32_t sB = sb + A_STAGE;

        #pragma unroll
        for (int t = 0; t < 2; t++) {
            // B fragments for 2 k8-steps: one float4 per ni
            float4 bf[8];
            #pragma unroll
            for (int ni = 0; ni < 8; ni++)
                bf[ni] = *reinterpret_cast<const float4*>(
                    smem + (sB - sbase) + bBase[ni] + t * 16);

            #pragma unroll
            for (int s2 = 0; s2 < 2; s2++) {
                const int s = 2 * t + s2;
                uint32_t a[4][4];
                #pragma unroll
                for (int mi = 0; mi < 4; mi++) {
                    const float* ar = reinterpret_cast<const float*>(smem)
                                    + (sA - sbase) / 4 + aBase[mi] + s * 8;
                    a[mi][0] = f2tf32(ar[0]);          // (g,    c)
                    a[mi][1] = f2tf32(ar[8 * 36]);     // (g+8,  c)
                    a[mi][2] = f2tf32(ar[4]);          // (g,    c+4)
                    a[mi][3] = f2tf32(ar[8 * 36 + 4]); // (g+8,  c+4)
                }
                #pragma unroll
                for (int mi = 0; mi < 4; mi++)
                    #pragma unroll
                    for (int ni = 0; ni < 8; ni++) {
                        const uint32_t b0 = (s2 == 0)
                            ? __float_as_uint(bf[ni].x) : __float_as_uint(bf[ni].z);
                        const uint32_t b1 = (s2 == 0)
                            ? __float_as_uint(bf[ni].y) : __float_as_uint(bf[ni].w);
                        mma_tf32(acc[mi][ni], a[mi], b0, b1);
                    }
            }
        }
        __syncthreads();
    }

    // epilogue (C layout identical to m16n8k16 path)
    const int eg = lane >> 2;
    const int tg = lane & 3;
    #pragma unroll
    for (int mi = 0; mi < 4; mi++) {
        const int r0 = row0 + wm * 64 + mi * 16 + eg;
        #pragma unroll
        for (int ni = 0; ni < 8; ni++) {
            const int cc = col0 + wn * 64 + ni * 8 + tg * 2;
            float b0 = 0.f, b1 = 0.f;
            if (bias) { b0 = bias[cc]; b1 = bias[cc + 1]; }
            float2 v0 = make_float2(acc[mi][ni][0] + b0, acc[mi][ni][1] + b1);
            float2 v1 = make_float2(acc[mi][ni][2] + b0, acc[mi][ni][3] + b1);
            *reinterpret_cast<float2*>(&C[(size_t)r0 * DIM + cc]) = v0;
            *reinterpret_cast<float2*>(&C[(size_t)(r0 + 8) * DIM + cc]) = v1;
        }
    }
}

// ---------------------------------------------------------------------------
// Per-token head-mixing attention + permuted fp32 store.
// ---------------------------------------------------------------------------
__global__ __launch_bounds__(128) void attn_kernel(
    const float* __restrict__ Q, const float* __restrict__ K,
    const float* __restrict__ V, float* __restrict__ Y)
{
    const int t = blockIdx.x;
    const int n = t & (SEQ - 1);
    const int b = t >> 11;

    const float* q = Q + (size_t)t * DIM;
    const float* k = K + (size_t)t * DIM;
    const float* v = V + (size_t)t * DIM;

    __shared__ float sq[HEADS * 65];
    __shared__ float sk[HEADS * 65];
    __shared__ float sv[DIM];
    __shared__ float sl[HEADS * HEADS];

    const int tid = threadIdx.x;

    #pragma unroll
    for (int i = tid; i < 256; i += 128) {
        const int r = i >> 4;
        const int cc = (i & 15) << 2;
        float4 a = reinterpret_cast<const float4*>(q)[i];
        sq[r * 65 + cc + 0] = a.x; sq[r * 65 + cc + 1] = a.y;
        sq[r * 65 + cc + 2] = a.z; sq[r * 65 + cc + 3] = a.w;
        float4 bb = reinterpret_cast<const float4*>(k)[i];
        sk[r * 65 + cc + 0] = bb.x; sk[r * 65 + cc + 1] = bb.y;
        sk[r * 65 + cc + 2] = bb.z; sk[r * 65 + cc + 3] = bb.w;
        reinterpret_cast<float4*>(sv)[i] = reinterpret_cast<const float4*>(v)[i];
    }
    __syncthreads();

    #pragma unroll
    for (int e = tid; e < 256; e += 128) {
        const int h = e >> 4;
        const int gg = e & 15;
        float s = 0.f;
        #pragma unroll
        for (int d = 0; d < HDIM; d++)
            s += sq[h * 65 + d] * sk[gg * 65 + d];
        sl[h * 16 + gg] = s * 0.125f;
    }
    __syncthreads();

    if (tid < HEADS) {
        float mx = -1e30f;
        #pragma unroll
        for (int gg = 0; gg < 16; gg++) mx = fmaxf(mx, sl[tid * 16 + gg]);
        float sum = 0.f;
        #pragma unroll
        for (int gg = 0; gg < 16; gg++) {
            const float e = __expf(sl[tid * 16 + gg] - mx);
            sl[tid * 16 + gg] = e;
            sum += e;
        }
        const float inv = 1.f / sum;
        #pragma unroll
        for (int gg = 0; gg < 16; gg++) sl[tid * 16 + gg] *= inv;
    }
    __syncthreads();

    float* yb = Y + (size_t)b * (SEQ * DIM);
    #pragma unroll
    for (int e = tid; e < 1024; e += 128) {
        const int h = e >> 6;
        const int d = e & 63;
        float s = 0.f;
        #pragma unroll
        for (int gg = 0; gg < 16; gg++)
            s += sl[h * 16 + gg] * sv[gg * 64 + d];
        const int nn = h * 128 + (n >> 4);
        const int cc = ((n & 15) << 6) + d;
        yb[(size_t)nn * DIM + cc] = s;
    }
}

// ---------------------------------------------------------------------------
// kernel_launch
// ---------------------------------------------------------------------------
extern "C" void kernel_launch(void* const* d_in, const int* in_sizes, int n_in,
                              void* d_out, int out_size)
{
    const float* query = (const float*)d_in[0];
    const float* key   = (const float*)d_in[1];
    const float* value = (const float*)d_in[2];
    const float* Wq    = (const float*)d_in[5];
    const float* Wk    = (const float*)d_in[6];
    const float* Wv    = (const float*)d_in[7];
    const float* Wp    = (const float*)d_in[8];
    const float* bp    = (const float*)d_in[9];
    float* out = (float*)d_out;

    float *Qb, *Kb, *Vb, *Yb, *Wt;
    cudaGetSymbolAddress((void**)&Qb, g_Q);
    cudaGetSymbolAddress((void**)&Kb, g_K);
    cudaGetSymbolAddress((void**)&Vb, g_V);
    cudaGetSymbolAddress((void**)&Yb, g_Y);
    cudaGetSymbolAddress((void**)&Wt, g_Wt);

    cudaFuncSetAttribute(gemm_tf32_kernel,
                         cudaFuncAttributeMaxDynamicSharedMemorySize, GEMM_SMEM);

    // weight prep: tf32-round + interleave (4M elems)
    prep_w_kernel<<<4 * DIM * DIM / 256, 256>>>(Wq, Wk, Wv, Wp, Wt);

    const size_t WSZ = (size_t)DIM * DIM;
    // merged Q/K/V projections: grid.z = 3
    {
        dim3 grid(DIM / GBN, TOKENS / GBM, 3);   // (4, 128, 3)
        gemm_tf32_kernel<<<grid, 256, GEMM_SMEM>>>(
            query, key, value,
            Wt + 0 * WSZ, Wt + 1 * WSZ, Wt + 2 * WSZ,
            Qb, Kb, Vb, nullptr);
    }

    attn_kernel<<<TOKENS, 128>>>(Qb, Kb, Vb, Yb);

    // output projection (+bias)
    {
        dim3 grid(DIM / GBN, TOKENS / GBM, 1);   // (4, 128, 1)
        gemm_tf32_kernel<<<grid, 256, GEMM_SMEM>>>(
            Yb, Yb, Yb,
            Wt + 3 * WSZ, Wt + 3 * WSZ, Wt + 3 * WSZ,
            out, out, out, bp);
    }
}